// round 2
// baseline (speedup 1.0000x reference)
#include <cuda_runtime.h>
#include <stdint.h>

#define NN_  100000
#define EE_  1600000
#define DH   128
#define DL   64
#define TOT_CT 6400000u   // N*64 elements of eps

// ---------------- device scratch (no cudaMalloc allowed) ----------------
__device__ float g_h0  [NN_ * DH];   // pre-aggregation buffer (reused 3x)
__device__ float g_h   [NN_ * DH];   // h after encoder layer
__device__ float g_agg2[NN_ * DH];   // aggregated [mu | logvar]
__device__ float g_deg [NN_];
__device__ float g_dinv_e[NN_];
__device__ float g_dinv_1[NN_];
__device__ int   g_cnt [NN_];
__device__ int   g_base[NN_];
__device__ int   g_fill[NN_];
__device__ int   g_csrc[EE_];
__device__ float g_cw  [EE_];
__device__ int   g_bsum[128];
__device__ float g_bias2[DH];
__device__ int   g_is64;

// ---------------- edge_index dtype detection (int64 vs int32) ----------------
__global__ void detect_kernel(const unsigned* __restrict__ q) {
    // If data is int64 little-endian with values < 2^32, every odd 32-bit word
    // of the first 128 entries is 0. For int32 data those words are random
    // node indices (P(all zero) ~ (1e-5)^128 ~ 0).
    unsigned v = q[threadIdx.x * 2 + 1];
    int any = __syncthreads_or(v != 0u);
    if (threadIdx.x == 0) g_is64 = any ? 0 : 1;
}

__device__ __forceinline__ int2 load_edge(const void* p, int e, int is64) {
    if (is64) {
        const long long* q = (const long long*)p;
        return make_int2((int)q[e], (int)q[EE_ + e]);
    } else {
        const int* q = (const int*)p;
        return make_int2(q[e], q[EE_ + e]);
    }
}

// ---------------- init: zero counters, build concat bias ----------------
__global__ void init_kernel(const float* __restrict__ b_mu, const float* __restrict__ b_lv) {
    int i = blockIdx.x * blockDim.x + threadIdx.x;
    if (i < NN_) {
        g_deg[i]  = 0.f;
        g_cnt[i]  = 0;
        g_fill[i] = 0;
    }
    if (i < DL)       g_bias2[i]      = b_mu[i];
    else if (i < DH)  g_bias2[i]      = b_lv[i - DL];
}

// ---------------- degree accumulation ----------------
__global__ void deg_kernel(const void* __restrict__ ei, const float* __restrict__ ew) {
    int e = blockIdx.x * blockDim.x + threadIdx.x;
    if (e >= EE_) return;
    int is64 = g_is64;
    int2 sd = load_edge(ei, e, is64);
    atomicAdd(&g_deg[sd.y], ew[e]);
    atomicAdd(&g_cnt[sd.y], 1);
}

// ---------------- exclusive scan of g_cnt -> g_base (3 kernels) ----------------
__global__ void scan1_kernel() {
    __shared__ int sh[1024];
    int i = blockIdx.x * 1024 + threadIdx.x;
    int v = (i < NN_) ? g_cnt[i] : 0;
    sh[threadIdx.x] = v;
    __syncthreads();
    #pragma unroll
    for (int off = 1; off < 1024; off <<= 1) {
        int t = (threadIdx.x >= off) ? sh[threadIdx.x - off] : 0;
        __syncthreads();
        sh[threadIdx.x] += t;
        __syncthreads();
    }
    if (i < NN_) g_base[i] = sh[threadIdx.x] - v;  // exclusive
    if (threadIdx.x == 1023) g_bsum[blockIdx.x] = sh[1023];
}

__global__ void scan2_kernel(int nblocks) {
    __shared__ int sh[128];
    int v = (threadIdx.x < nblocks) ? g_bsum[threadIdx.x] : 0;
    sh[threadIdx.x] = v;
    __syncthreads();
    #pragma unroll
    for (int off = 1; off < 128; off <<= 1) {
        int t = (threadIdx.x >= off) ? sh[threadIdx.x - off] : 0;
        __syncthreads();
        sh[threadIdx.x] += t;
        __syncthreads();
    }
    g_bsum[threadIdx.x] = sh[threadIdx.x] - v;  // exclusive
}

__global__ void scan3_kernel() {
    int i = blockIdx.x * blockDim.x + threadIdx.x;
    if (i >= NN_) return;
    g_base[i] += g_bsum[i >> 10];
    g_dinv_e[i] = rsqrtf(g_deg[i] + 1.0f);              // +1: self-loop weight 1
    g_dinv_1[i] = rsqrtf((float)g_cnt[i] + 1.0f);       // unweighted degree + self
}

// ---------------- CSR fill ----------------
__global__ void fill_kernel(const void* __restrict__ ei, const float* __restrict__ ew) {
    int e = blockIdx.x * blockDim.x + threadIdx.x;
    if (e >= EE_) return;
    int is64 = g_is64;
    int2 sd = load_edge(ei, e, is64);
    int slot = g_base[sd.y] + atomicAdd(&g_fill[sd.y], 1);
    g_csrc[slot] = sd.x;
    g_cw[slot]   = ew[e];
}

// ---------------- SGEMM: C[M,NCOL](+coff into ldc-stride) = A[M,K] * W[K,NCOL] ----------------
// 64x64 block tile, 4x4 register tile, 256 threads, BK=16
__global__ void sgemm_kernel(const float* __restrict__ A, const float* __restrict__ W,
                             float* __restrict__ C, int M, int K, int NCOL, int ldc, int coff) {
    __shared__ float As[16][64];
    __shared__ float Bs[16][64];
    int tid = threadIdx.x;
    int tr = tid >> 4;           // 0..15 (row group)
    int tc = tid & 15;           // 0..15 (col group)
    int rowbase = blockIdx.y * 64;
    int colbase = blockIdx.x * 64;

    float acc[4][4];
    #pragma unroll
    for (int i = 0; i < 4; i++)
        #pragma unroll
        for (int j = 0; j < 4; j++) acc[i][j] = 0.f;

    int lrow = tid >> 2;          // 0..63
    int lkq  = (tid & 3) * 4;     // 0,4,8,12
    int brow = tid >> 4;          // 0..15
    int bcol = (tid & 15) * 4;    // 0..60

    for (int k0 = 0; k0 < K; k0 += 16) {
        float4 av = make_float4(0.f, 0.f, 0.f, 0.f);
        int gr = rowbase + lrow;
        if (gr < M) av = *(const float4*)&A[(size_t)gr * K + k0 + lkq];
        As[lkq + 0][lrow] = av.x;
        As[lkq + 1][lrow] = av.y;
        As[lkq + 2][lrow] = av.z;
        As[lkq + 3][lrow] = av.w;
        float4 bv = *(const float4*)&W[(size_t)(k0 + brow) * NCOL + colbase + bcol];
        *(float4*)&Bs[brow][bcol] = bv;
        __syncthreads();
        #pragma unroll
        for (int k = 0; k < 16; k++) {
            float4 a = *(const float4*)&As[k][tr * 4];
            float4 b = *(const float4*)&Bs[k][tc * 4];
            acc[0][0] = fmaf(a.x, b.x, acc[0][0]);
            acc[0][1] = fmaf(a.x, b.y, acc[0][1]);
            acc[0][2] = fmaf(a.x, b.z, acc[0][2]);
            acc[0][3] = fmaf(a.x, b.w, acc[0][3]);
            acc[1][0] = fmaf(a.y, b.x, acc[1][0]);
            acc[1][1] = fmaf(a.y, b.y, acc[1][1]);
            acc[1][2] = fmaf(a.y, b.z, acc[1][2]);
            acc[1][3] = fmaf(a.y, b.w, acc[1][3]);
            acc[2][0] = fmaf(a.z, b.x, acc[2][0]);
            acc[2][1] = fmaf(a.z, b.y, acc[2][1]);
            acc[2][2] = fmaf(a.z, b.z, acc[2][2]);
            acc[2][3] = fmaf(a.z, b.w, acc[2][3]);
            acc[3][0] = fmaf(a.w, b.x, acc[3][0]);
            acc[3][1] = fmaf(a.w, b.y, acc[3][1]);
            acc[3][2] = fmaf(a.w, b.z, acc[3][2]);
            acc[3][3] = fmaf(a.w, b.w, acc[3][3]);
        }
        __syncthreads();
    }
    #pragma unroll
    for (int i = 0; i < 4; i++) {
        int gr = rowbase + tr * 4 + i;
        if (gr < M) {
            float4 o = make_float4(acc[i][0], acc[i][1], acc[i][2], acc[i][3]);
            *(float4*)&C[(size_t)gr * ldc + coff + colbase + tc * 4] = o;
        }
    }
}

// ---------------- aggregation: one warp per destination node, 128 cols ----------------
// hout[d] = bias + hin[d]*dinv[d]^2 (self loop) + sum_{e in CSR[d]} hin[src]*dinv[src]*w*dinv[d]
__global__ void agg_kernel(const float* __restrict__ hin, float* __restrict__ hout,
                           const float* __restrict__ dinv, const float* __restrict__ bias,
                           int use_w) {
    int w = (blockIdx.x * blockDim.x + threadIdx.x) >> 5;
    int lane = threadIdx.x & 31;
    if (w >= NN_) return;
    float dd = dinv[w];
    float4 b4 = *(const float4*)&bias[lane * 4];
    float4 sv = *(const float4*)&hin[(size_t)w * DH + lane * 4];
    float sn = dd * dd;
    float4 acc;
    acc.x = fmaf(sv.x, sn, b4.x);
    acc.y = fmaf(sv.y, sn, b4.y);
    acc.z = fmaf(sv.z, sn, b4.z);
    acc.w = fmaf(sv.w, sn, b4.w);
    int beg = g_base[w];
    int end = beg + g_cnt[w];
    for (int p = beg; p < end; p++) {
        int s = g_csrc[p];
        float nrm = dinv[s] * dd;
        if (use_w) nrm *= g_cw[p];
        float4 v = *(const float4*)&hin[(size_t)s * DH + lane * 4];
        acc.x = fmaf(nrm, v.x, acc.x);
        acc.y = fmaf(nrm, v.y, acc.y);
        acc.z = fmaf(nrm, v.z, acc.z);
        acc.w = fmaf(nrm, v.w, acc.w);
    }
    *(float4*)&hout[(size_t)w * DH + lane * 4] = acc;
}

// ---------------- threefry2x32 (JAX key(42)), PARTITIONABLE mode ----------------
// Modern JAX default (jax_threefry_partitionable=True): element i gets counter
// (hi32(i), lo32(i)) = (0, i) for i < 2^32, and the 32-bit output is out0 ^ out1.
__device__ __forceinline__ void tf_round(uint32_t& x0, uint32_t& x1, int r) {
    x0 += x1;
    x1 = (x1 << r) | (x1 >> (32 - r));
    x1 ^= x0;
}

__device__ __forceinline__ uint32_t threefry_bits_partitionable(uint32_t i) {
    const uint32_t ks0 = 0u, ks1 = 42u, ks2 = 0x1BD11BDAu ^ 42u;
    uint32_t x0 = 0u + ks0, x1 = i + ks1;   // c0 = counts_hi = 0, c1 = counts_lo = i
    tf_round(x0, x1, 13); tf_round(x0, x1, 15); tf_round(x0, x1, 26); tf_round(x0, x1, 6);
    x0 += ks1; x1 += ks2 + 1u;
    tf_round(x0, x1, 17); tf_round(x0, x1, 29); tf_round(x0, x1, 16); tf_round(x0, x1, 24);
    x0 += ks2; x1 += ks0 + 2u;
    tf_round(x0, x1, 13); tf_round(x0, x1, 15); tf_round(x0, x1, 26); tf_round(x0, x1, 6);
    x0 += ks0; x1 += ks1 + 3u;
    tf_round(x0, x1, 17); tf_round(x0, x1, 29); tf_round(x0, x1, 16); tf_round(x0, x1, 24);
    x0 += ks1; x1 += ks2 + 4u;
    tf_round(x0, x1, 13); tf_round(x0, x1, 15); tf_round(x0, x1, 26); tf_round(x0, x1, 6);
    x0 += ks2; x1 += ks0 + 5u;
    return x0 ^ x1;
}

// XLA's fp32 erfinv (Giles polynomial) — must match XLA for the RNG path
__device__ __forceinline__ float erfinv_xla(float x) {
    float w = -log1pf(-x * x);
    float p;
    if (w < 5.0f) {
        w -= 2.5f;
        p = 2.81022636e-08f;
        p = fmaf(p, w, 3.43273939e-07f);
        p = fmaf(p, w, -3.5233877e-06f);
        p = fmaf(p, w, -4.39150654e-06f);
        p = fmaf(p, w, 0.00021858087f);
        p = fmaf(p, w, -0.00125372503f);
        p = fmaf(p, w, -0.00417768164f);
        p = fmaf(p, w, 0.246640727f);
        p = fmaf(p, w, 1.50140941f);
    } else {
        w = sqrtf(w) - 3.0f;
        p = -0.000200214257f;
        p = fmaf(p, w, 0.000100950558f);
        p = fmaf(p, w, 0.00134934322f);
        p = fmaf(p, w, -0.00367342844f);
        p = fmaf(p, w, 0.00573950773f);
        p = fmaf(p, w, -0.0076224613f);
        p = fmaf(p, w, 0.00943887047f);
        p = fmaf(p, w, 1.00167406f);
        p = fmaf(p, w, 2.83297682f);
    }
    return p * x;
}

__device__ __forceinline__ float bits_to_normal(uint32_t b) {
    float f = __uint_as_float((b >> 9) | 0x3f800000u) - 1.0f;  // [0,1)
    const float lo = -0.99999994f;      // nextafter(-1,0)
    float u = __fmul_rn(f, 2.0f);       // span (hi-lo) rounds to exactly 2.0f
    u = __fadd_rn(u, lo);
    u = fmaxf(u, lo);
    return 1.4142135623730951f * erfinv_xla(u);   // f32 sqrt(2) rounding == numpy's
}

__global__ void z_kernel(float* __restrict__ o_z, float* __restrict__ o_mu,
                         float* __restrict__ o_lv) {
    unsigned li = blockIdx.x * blockDim.x + threadIdx.x;
    if (li >= TOT_CT) return;
    unsigned r = li >> 6, c = li & 63u;
    float mu = g_agg2[(size_t)r * DH + c];
    float lv = g_agg2[(size_t)r * DH + DL + c];
    uint32_t bits = threefry_bits_partitionable(li);
    float eps = bits_to_normal(bits);
    float z = __fadd_rn(mu, __fmul_rn(eps, expf(0.5f * lv)));
    o_z[li]  = z;
    o_mu[li] = mu;
    o_lv[li] = lv;
}

// ---------------- launch ----------------
extern "C" void kernel_launch(void* const* d_in, const int* in_sizes, int n_in,
                              void* d_out, int out_size) {
    const float* x     = (const float*)d_in[0];
    const float* ew    = (const float*)d_in[1];
    const float* W_enc = (const float*)d_in[2];
    const float* b_enc = (const float*)d_in[3];
    const float* W_mu  = (const float*)d_in[4];
    const float* b_mu  = (const float*)d_in[5];
    const float* W_lv  = (const float*)d_in[6];
    const float* b_lv  = (const float*)d_in[7];
    const float* W_dec = (const float*)d_in[8];
    const float* b_dec = (const float*)d_in[9];
    const void*  eidx  = d_in[10];

    float* out   = (float*)d_out;
    float* o_z   = out;                       // [N,64]
    float* o_rec = out + (size_t)NN_ * DL;    // [N,128]
    float* o_mu  = o_rec + (size_t)NN_ * DH;  // [N,64]
    float* o_lv  = o_mu + (size_t)NN_ * DL;   // [N,64]

    float *p_h0, *p_h, *p_agg2, *p_dinv_e, *p_dinv_1, *p_bias2;
    cudaGetSymbolAddress((void**)&p_h0, g_h0);
    cudaGetSymbolAddress((void**)&p_h, g_h);
    cudaGetSymbolAddress((void**)&p_agg2, g_agg2);
    cudaGetSymbolAddress((void**)&p_dinv_e, g_dinv_e);
    cudaGetSymbolAddress((void**)&p_dinv_1, g_dinv_1);
    cudaGetSymbolAddress((void**)&p_bias2, g_bias2);

    const int NB_SCAN = (NN_ + 1023) / 1024;           // 98

    detect_kernel<<<1, 128>>>((const unsigned*)eidx);
    init_kernel<<<(NN_ + 255) / 256, 256>>>(b_mu, b_lv);
    deg_kernel<<<(EE_ + 255) / 256, 256>>>(eidx, ew);
    scan1_kernel<<<NB_SCAN, 1024>>>();
    scan2_kernel<<<1, 128>>>(NB_SCAN);
    scan3_kernel<<<(NN_ + 255) / 256, 256>>>();
    fill_kernel<<<(EE_ + 255) / 256, 256>>>(eidx, ew);

    dim3 gemm_grid_full(2, (NN_ + 63) / 64);
    dim3 gemm_grid_half(1, (NN_ + 63) / 64);

    // encoder: h0 = x @ W_enc ; h = agg_w(h0) + b_enc
    sgemm_kernel<<<gemm_grid_full, 256>>>(x, W_enc, p_h0, NN_, DH, DH, DH, 0);
    agg_kernel<<<(NN_ * 32 + 255) / 256, 256>>>(p_h0, p_h, p_dinv_e, b_enc, 1);

    // mu|lv: h0[:, :64] = h @ W_mu, h0[:, 64:] = h @ W_lv ; agg2 = agg(h0) + [b_mu|b_lv]
    sgemm_kernel<<<gemm_grid_half, 256>>>(p_h, W_mu, p_h0, NN_, DH, DL, DH, 0);
    sgemm_kernel<<<gemm_grid_half, 256>>>(p_h, W_lv, p_h0, NN_, DH, DL, DH, DL);
    agg_kernel<<<(NN_ * 32 + 255) / 256, 256>>>(p_h0, p_agg2, p_dinv_1, p_bias2, 0);

    // reparameterize (writes z, mu, logvar to d_out)
    z_kernel<<<(TOT_CT + 255) / 256, 256>>>(o_z, o_mu, o_lv);

    // decoder: h0 = z @ W_dec ; recon = agg(h0) + b_dec
    sgemm_kernel<<<gemm_grid_full, 256>>>(o_z, W_dec, p_h0, NN_, DL, DH, DH, 0);
    agg_kernel<<<(NN_ * 32 + 255) / 256, 256>>>(p_h0, o_rec, p_dinv_1, b_dec, 0);
}

// round 4
// speedup vs baseline: 1.1075x; 1.1075x over previous
#include <cuda_runtime.h>
#include <cuda_bf16.h>
#include <stdint.h>

#define NN_  100000
#define EE_  1600000
#define DH   128
#define DL   64
#define TOT_CT 6400000u   // N*64 elements of eps

// ---------------- device scratch (no cudaMalloc allowed) ----------------
__device__ float g_h0  [NN_ * DH];   // pre-aggregation buffer (reused)
__device__ float g_h   [NN_ * DH];   // h after encoder layer
__device__ float g_agg2[NN_ * DH];   // [mu|lv] agg, later reused as t = A*z (N x 64)
__device__ float g_deg [NN_];
__device__ float g_dinv_e[NN_];
__device__ float g_dinv_1[NN_];
__device__ int   g_cnt [NN_];
__device__ int   g_base[NN_];
__device__ int   g_fill[NN_];
__device__ int   g_csrc[EE_];
__device__ float g_cw  [EE_];
__device__ int   g_bsum[128];
__device__ float g_bias2[DH];
__device__ int   g_is64;

// Preconverted weight operand images: W^T as bf16 hi/lo, row-major [128][KP]
// KP = K + 8 pad (enc/mid K=128 -> KP=136 ; dec K=64 -> KP=72)
__device__ __align__(16) __nv_bfloat16 g_wt_enc_h[128 * 136];
__device__ __align__(16) __nv_bfloat16 g_wt_enc_l[128 * 136];
__device__ __align__(16) __nv_bfloat16 g_wt_mid_h[128 * 136];
__device__ __align__(16) __nv_bfloat16 g_wt_mid_l[128 * 136];
__device__ __align__(16) __nv_bfloat16 g_wt_dec_h[128 * 72];
__device__ __align__(16) __nv_bfloat16 g_wt_dec_l[128 * 72];

// ---------------- edge_index dtype detection ----------------
__global__ void detect_kernel(const unsigned* __restrict__ q) {
    unsigned v = q[threadIdx.x * 2 + 1];
    int any = __syncthreads_or(v != 0u);
    if (threadIdx.x == 0) g_is64 = any ? 0 : 1;
}

__device__ __forceinline__ int2 load_edge(const void* p, int e, int is64) {
    if (is64) {
        const long long* q = (const long long*)p;
        return make_int2((int)q[e], (int)q[EE_ + e]);
    } else {
        const int* q = (const int*)p;
        return make_int2(q[e], q[EE_ + e]);
    }
}

// ---------------- init ----------------
__global__ void init_kernel(const float* __restrict__ b_mu, const float* __restrict__ b_lv) {
    int i = blockIdx.x * blockDim.x + threadIdx.x;
    if (i < NN_) {
        g_deg[i]  = 0.f;
        g_cnt[i]  = 0;
        g_fill[i] = 0;
    }
    if (i < DL)       g_bias2[i] = b_mu[i];
    else if (i < DH)  g_bias2[i] = b_lv[i - DL];
}

// ---------------- degree accumulation ----------------
__global__ void deg_kernel(const void* __restrict__ ei, const float* __restrict__ ew) {
    int e = blockIdx.x * blockDim.x + threadIdx.x;
    if (e >= EE_) return;
    int is64 = g_is64;
    int2 sd = load_edge(ei, e, is64);
    atomicAdd(&g_deg[sd.y], ew[e]);
    atomicAdd(&g_cnt[sd.y], 1);
}

// ---------------- scans ----------------
__global__ void scan1_kernel() {
    __shared__ int sh[1024];
    int i = blockIdx.x * 1024 + threadIdx.x;
    int v = (i < NN_) ? g_cnt[i] : 0;
    sh[threadIdx.x] = v;
    __syncthreads();
    #pragma unroll
    for (int off = 1; off < 1024; off <<= 1) {
        int t = (threadIdx.x >= off) ? sh[threadIdx.x - off] : 0;
        __syncthreads();
        sh[threadIdx.x] += t;
        __syncthreads();
    }
    if (i < NN_) g_base[i] = sh[threadIdx.x] - v;
    if (threadIdx.x == 1023) g_bsum[blockIdx.x] = sh[1023];
}

__global__ void scan2_kernel(int nblocks) {
    __shared__ int sh[128];
    int v = (threadIdx.x < nblocks) ? g_bsum[threadIdx.x] : 0;
    sh[threadIdx.x] = v;
    __syncthreads();
    #pragma unroll
    for (int off = 1; off < 128; off <<= 1) {
        int t = (threadIdx.x >= off) ? sh[threadIdx.x - off] : 0;
        __syncthreads();
        sh[threadIdx.x] += t;
        __syncthreads();
    }
    g_bsum[threadIdx.x] = sh[threadIdx.x] - v;
}

__global__ void scan3_kernel() {
    int i = blockIdx.x * blockDim.x + threadIdx.x;
    if (i >= NN_) return;
    g_base[i] += g_bsum[i >> 10];
    g_dinv_e[i] = rsqrtf(g_deg[i] + 1.0f);
    g_dinv_1[i] = rsqrtf((float)g_cnt[i] + 1.0f);
}

// ---------------- CSR fill ----------------
__global__ void fill_kernel(const void* __restrict__ ei, const float* __restrict__ ew) {
    int e = blockIdx.x * blockDim.x + threadIdx.x;
    if (e >= EE_) return;
    int is64 = g_is64;
    int2 sd = load_edge(ei, e, is64);
    int slot = g_base[sd.y] + atomicAdd(&g_fill[sd.y], 1);
    g_csrc[slot] = sd.x;
    g_cw[slot]   = ew[e];
}

// ---------------- weight convert: W[k][n] -> W^T[n][k] bf16 hi/lo, padded rows ----------------
__device__ __forceinline__ void split_bf16(float v, __nv_bfloat16& h, __nv_bfloat16& l) {
    h = __float2bfloat16(v);
    l = __float2bfloat16(v - __bfloat162float(h));
}

__global__ void wconv_kernel(const float* __restrict__ W_enc, const float* __restrict__ W_mu,
                             const float* __restrict__ W_lv,  const float* __restrict__ W_dec) {
    int idx = blockIdx.x * blockDim.x + threadIdx.x;
    if (idx >= 128 * 136) return;
    int n = idx / 136, k = idx % 136;
    __nv_bfloat16 h, l;
    // enc / mid: K=128, pad k>=128 with zeros
    float ve = (k < 128) ? W_enc[k * 128 + n] : 0.f;
    split_bf16(ve, h, l);
    g_wt_enc_h[idx] = h; g_wt_enc_l[idx] = l;
    float vm = 0.f;
    if (k < 128) vm = (n < 64) ? W_mu[k * 64 + n] : W_lv[k * 64 + (n - 64)];
    split_bf16(vm, h, l);
    g_wt_mid_h[idx] = h; g_wt_mid_l[idx] = l;
    // dec: K=64, KP=72
    if (k < 72) {
        int di = n * 72 + k;
        float vd = (k < 64) ? W_dec[k * 128 + n] : 0.f;
        split_bf16(vd, h, l);
        g_wt_dec_h[di] = h; g_wt_dec_l[di] = l;
    }
}

// ======================= HMMA GEMM (mma.sync m16n8k16 bf16) =======================
__device__ __forceinline__ uint32_t smem_u32(const void* p) {
    uint32_t a;
    asm("{ .reg .u64 t; cvta.to.shared.u64 t, %1; cvt.u32.u64 %0, t; }" : "=r"(a) : "l"(p));
    return a;
}

__device__ __forceinline__ void ldm_x4(uint32_t addr, uint32_t& r0, uint32_t& r1,
                                       uint32_t& r2, uint32_t& r3) {
    asm volatile("ldmatrix.sync.aligned.m8n8.x4.shared.b16 {%0,%1,%2,%3}, [%4];"
                 : "=r"(r0), "=r"(r1), "=r"(r2), "=r"(r3) : "r"(addr));
}

__device__ __forceinline__ void mma16816(float* c, const uint32_t* a, const uint32_t* b) {
    asm volatile(
        "mma.sync.aligned.m16n8k16.row.col.f32.bf16.bf16.f32 "
        "{%0,%1,%2,%3}, {%4,%5,%6,%7}, {%8,%9}, {%0,%1,%2,%3};"
        : "+f"(c[0]), "+f"(c[1]), "+f"(c[2]), "+f"(c[3])
        : "r"(a[0]), "r"(a[1]), "r"(a[2]), "r"(a[3]), "r"(b[0]), "r"(b[1]));
}

// C[M,128] = A[M,KDIM] @ W^T  with bf16x3 split (Ah*Bh + Ah*Bl + Al*Bh) + optional bias.
// CTA tile: 128 x 128. 256 threads = 8 warps (2 x 4), warp tile 64 x 32.
template<int KDIM>
__global__ void __launch_bounds__(256, 1) hmma_gemm_kernel(
        const float* __restrict__ A, int M,
        const __nv_bfloat16* __restrict__ Bh_img, const __nv_bfloat16* __restrict__ Bl_img,
        float* __restrict__ C, const float* __restrict__ bias) {
    constexpr int KP = KDIM + 8;           // padded row stride (elements)
    constexpr int SZ = 128 * KP;           // elements per image
    extern __shared__ __align__(16) __nv_bfloat16 smem[];
    __nv_bfloat16* sAh = smem;
    __nv_bfloat16* sAl = smem + SZ;
    __nv_bfloat16* sBh = smem + 2 * SZ;
    __nv_bfloat16* sBl = smem + 3 * SZ;

    int tid = threadIdx.x, wid = tid >> 5, lane = tid & 31;
    int rowbase = blockIdx.x * 128;

    // ---- stage B: verbatim copy of preconverted images ----
    {
        const uint4* gh = (const uint4*)Bh_img;
        const uint4* gl = (const uint4*)Bl_img;
        uint4* th = (uint4*)sBh;
        uint4* tl = (uint4*)sBl;
        constexpr int NV = SZ * 2 / 16;
        for (int i = tid; i < NV; i += 256) { th[i] = gh[i]; tl[i] = gl[i]; }
    }

    // ---- stage A: fp32 -> bf16 hi/lo split into padded rows ----
    {
        constexpr int C4 = KDIM / 4;
        for (int i = tid; i < 128 * C4; i += 256) {
            int row = i / C4, col = (i % C4) * 4;
            float4 av = make_float4(0.f, 0.f, 0.f, 0.f);
            if (rowbase + row < M)
                av = *(const float4*)&A[(size_t)(rowbase + row) * KDIM + col];
            __nv_bfloat16 h0, h1, h2, h3, l0, l1, l2, l3;
            split_bf16(av.x, h0, l0); split_bf16(av.y, h1, l1);
            split_bf16(av.z, h2, l2); split_bf16(av.w, h3, l3);
            uint2 hv, lv;
            hv.x = ((uint32_t)__bfloat16_as_ushort(h1) << 16) | __bfloat16_as_ushort(h0);
            hv.y = ((uint32_t)__bfloat16_as_ushort(h3) << 16) | __bfloat16_as_ushort(h2);
            lv.x = ((uint32_t)__bfloat16_as_ushort(l1) << 16) | __bfloat16_as_ushort(l0);
            lv.y = ((uint32_t)__bfloat16_as_ushort(l3) << 16) | __bfloat16_as_ushort(l2);
            int off = row * KP + col;
            *(uint2*)&sAh[off] = hv;
            *(uint2*)&sAl[off] = lv;
        }
        // zero the pad columns (k >= KDIM) so ldmatrix of pad region is harmless
        for (int i = tid; i < 128 * 8 / 4; i += 256) {
            int row = i / 2, seg = i % 2;
            int off = row * KP + KDIM + seg * 4;
            *(uint2*)&sAh[off] = make_uint2(0u, 0u);
            *(uint2*)&sAl[off] = make_uint2(0u, 0u);
        }
    }
    __syncthreads();

    // ---- compute: warp (2 x 4) grid, warp tile 64 x 32 ----
    int warp_m = (wid >> 2) * 64;          // 0 or 64
    int warp_n = (wid & 3) * 32;           // 0,32,64,96

    float acc[4][4][4];                    // [mi][ni][reg]
    #pragma unroll
    for (int a = 0; a < 4; a++)
        #pragma unroll
        for (int b = 0; b < 4; b++)
            #pragma unroll
            for (int r = 0; r < 4; r++) acc[a][b][r] = 0.f;

    uint32_t sAh_base = smem_u32(sAh), sAl_base = smem_u32(sAl);
    uint32_t sBh_base = smem_u32(sBh), sBl_base = smem_u32(sBl);

    // ldmatrix lane addressing (x4): g = lane>>3
    //  A tiles: {m0-7,k0},{m8-15,k0},{m0-7,k8},{m8-15,k8}
    int gA = lane >> 3;
    int a_row_off = (lane & 7) + (gA & 1) * 8;
    int a_col_off = (gA >> 1) * 8;
    //  B tiles: {n0-7,k0},{n0-7,k8},{n8-15,k0},{n8-15,k8}
    int gB = lane >> 3;
    int b_row_off = (lane & 7) + (gB >> 1) * 8;
    int b_col_off = (gB & 1) * 8;

    constexpr int NSTEP = KDIM / 16;
    #pragma unroll
    for (int ks = 0; ks < NSTEP; ks++) {
        int k0 = ks * 16;
        // B fragments for this k-step: 4 n-frags (n8 each), hi & lo
        uint32_t bh[4][2], bl[4][2];
        #pragma unroll
        for (int ni2 = 0; ni2 < 2; ni2++) {
            uint32_t off = (uint32_t)((warp_n + ni2 * 16 + b_row_off) * KP + k0 + b_col_off) * 2;
            uint32_t r0, r1, r2, r3;
            ldm_x4(sBh_base + off, r0, r1, r2, r3);
            bh[ni2 * 2 + 0][0] = r0; bh[ni2 * 2 + 0][1] = r1;
            bh[ni2 * 2 + 1][0] = r2; bh[ni2 * 2 + 1][1] = r3;
            ldm_x4(sBl_base + off, r0, r1, r2, r3);
            bl[ni2 * 2 + 0][0] = r0; bl[ni2 * 2 + 0][1] = r1;
            bl[ni2 * 2 + 1][0] = r2; bl[ni2 * 2 + 1][1] = r3;
        }
        #pragma unroll
        for (int mi = 0; mi < 4; mi++) {
            uint32_t off = (uint32_t)((warp_m + mi * 16 + a_row_off) * KP + k0 + a_col_off) * 2;
            uint32_t ah[4], al[4];
            ldm_x4(sAh_base + off, ah[0], ah[1], ah[2], ah[3]);
            ldm_x4(sAl_base + off, al[0], al[1], al[2], al[3]);
            #pragma unroll
            for (int ni = 0; ni < 4; ni++) {
                mma16816(acc[mi][ni], ah, bh[ni]);
                mma16816(acc[mi][ni], ah, bl[ni]);
                mma16816(acc[mi][ni], al, bh[ni]);
            }
        }
    }

    // ---- epilogue ----
    int qr = lane >> 2;          // 0..7
    int qc = (lane & 3) * 2;     // 0,2,4,6
    #pragma unroll
    for (int mi = 0; mi < 4; mi++) {
        int r0 = rowbase + warp_m + mi * 16 + qr;
        #pragma unroll
        for (int ni = 0; ni < 4; ni++) {
            int col = warp_n + ni * 8 + qc;
            float bx = 0.f, by = 0.f;
            if (bias) { bx = bias[col]; by = bias[col + 1]; }
            if (r0 < M) {
                float2 v = make_float2(acc[mi][ni][0] + bx, acc[mi][ni][1] + by);
                *(float2*)&C[(size_t)r0 * 128 + col] = v;
            }
            if (r0 + 8 < M) {
                float2 v = make_float2(acc[mi][ni][2] + bx, acc[mi][ni][3] + by);
                *(float2*)&C[(size_t)(r0 + 8) * 128 + col] = v;
            }
        }
    }
}

// ---------------- aggregation: one warp per destination node, 128 cols ----------------
__global__ void agg_kernel(const float* __restrict__ hin, float* __restrict__ hout,
                           const float* __restrict__ dinv, const float* __restrict__ bias,
                           int use_w) {
    int w = (blockIdx.x * blockDim.x + threadIdx.x) >> 5;
    int lane = threadIdx.x & 31;
    if (w >= NN_) return;
    float dd = dinv[w];
    float4 b4 = *(const float4*)&bias[lane * 4];
    float4 sv = *(const float4*)&hin[(size_t)w * DH + lane * 4];
    float sn = dd * dd;
    float4 acc;
    acc.x = fmaf(sv.x, sn, b4.x);
    acc.y = fmaf(sv.y, sn, b4.y);
    acc.z = fmaf(sv.z, sn, b4.z);
    acc.w = fmaf(sv.w, sn, b4.w);
    int beg = g_base[w];
    int end = beg + g_cnt[w];
    for (int p = beg; p < end; p++) {
        int s = g_csrc[p];
        float nrm = dinv[s] * dd;
        if (use_w) nrm *= g_cw[p];
        float4 v = *(const float4*)&hin[(size_t)s * DH + lane * 4];
        acc.x = fmaf(nrm, v.x, acc.x);
        acc.y = fmaf(nrm, v.y, acc.y);
        acc.z = fmaf(nrm, v.z, acc.z);
        acc.w = fmaf(nrm, v.w, acc.w);
    }
    *(float4*)&hout[(size_t)w * DH + lane * 4] = acc;
}

// ---------------- aggregation over 64-dim z (decoder reorder) ----------------
__global__ void agg64_kernel(const float* __restrict__ z, float* __restrict__ t,
                             const float* __restrict__ dinv) {
    int w = (blockIdx.x * blockDim.x + threadIdx.x) >> 5;
    int lane = threadIdx.x & 31;
    if (w >= NN_) return;
    float dd = dinv[w];
    float sn = dd * dd;
    float2 sv = *(const float2*)&z[(size_t)w * DL + lane * 2];
    float2 acc = make_float2(sv.x * sn, sv.y * sn);
    int beg = g_base[w];
    int end = beg + g_cnt[w];
    for (int p = beg; p < end; p++) {
        int s = g_csrc[p];
        float nrm = dinv[s] * dd;
        float2 v = *(const float2*)&z[(size_t)s * DL + lane * 2];
        acc.x = fmaf(nrm, v.x, acc.x);
        acc.y = fmaf(nrm, v.y, acc.y);
    }
    *(float2*)&t[(size_t)w * DL + lane * 2] = acc;
}

// ---------------- threefry2x32 (JAX key(42)), PARTITIONABLE mode ----------------
__device__ __forceinline__ void tf_round(uint32_t& x0, uint32_t& x1, int r) {
    x0 += x1;
    x1 = (x1 << r) | (x1 >> (32 - r));
    x1 ^= x0;
}

__device__ __forceinline__ uint32_t threefry_bits_partitionable(uint32_t i) {
    const uint32_t ks0 = 0u, ks1 = 42u, ks2 = 0x1BD11BDAu ^ 42u;
    uint32_t x0 = 0u + ks0, x1 = i + ks1;
    tf_round(x0, x1, 13); tf_round(x0, x1, 15); tf_round(x0, x1, 26); tf_round(x0, x1, 6);
    x0 += ks1; x1 += ks2 + 1u;
    tf_round(x0, x1, 17); tf_round(x0, x1, 29); tf_round(x0, x1, 16); tf_round(x0, x1, 24);
    x0 += ks2; x1 += ks0 + 2u;
    tf_round(x0, x1, 13); tf_round(x0, x1, 15); tf_round(x0, x1, 26); tf_round(x0, x1, 6);
    x0 += ks0; x1 += ks1 + 3u;
    tf_round(x0, x1, 17); tf_round(x0, x1, 29); tf_round(x0, x1, 16); tf_round(x0, x1, 24);
    x0 += ks1; x1 += ks2 + 4u;
    tf_round(x0, x1, 13); tf_round(x0, x1, 15); tf_round(x0, x1, 26); tf_round(x0, x1, 6);
    x0 += ks2; x1 += ks0 + 5u;
    return x0 ^ x1;
}

__device__ __forceinline__ float erfinv_xla(float x) {
    float w = -log1pf(-x * x);
    float p;
    if (w < 5.0f) {
        w -= 2.5f;
        p = 2.81022636e-08f;
        p = fmaf(p, w, 3.43273939e-07f);
        p = fmaf(p, w, -3.5233877e-06f);
        p = fmaf(p, w, -4.39150654e-06f);
        p = fmaf(p, w, 0.00021858087f);
        p = fmaf(p, w, -0.00125372503f);
        p = fmaf(p, w, -0.00417768164f);
        p = fmaf(p, w, 0.246640727f);
        p = fmaf(p, w, 1.50140941f);
    } else {
        w = sqrtf(w) - 3.0f;
        p = -0.000200214257f;
        p = fmaf(p, w, 0.000100950558f);
        p = fmaf(p, w, 0.00134934322f);
        p = fmaf(p, w, -0.00367342844f);
        p = fmaf(p, w, 0.00573950773f);
        p = fmaf(p, w, -0.0076224613f);
        p = fmaf(p, w, 0.00943887047f);
        p = fmaf(p, w, 1.00167406f);
        p = fmaf(p, w, 2.83297682f);
    }
    return p * x;
}

__device__ __forceinline__ float bits_to_normal(uint32_t b) {
    float f = __uint_as_float((b >> 9) | 0x3f800000u) - 1.0f;
    const float lo = -0.99999994f;
    float u = __fmul_rn(f, 2.0f);
    u = __fadd_rn(u, lo);
    u = fmaxf(u, lo);
    return 1.4142135623730951f * erfinv_xla(u);
}

__global__ void z_kernel(float* __restrict__ o_z, float* __restrict__ o_mu,
                         float* __restrict__ o_lv) {
    unsigned li = blockIdx.x * blockDim.x + threadIdx.x;
    if (li >= TOT_CT) return;
    unsigned r = li >> 6, c = li & 63u;
    float mu = g_agg2[(size_t)r * DH + c];
    float lv = g_agg2[(size_t)r * DH + DL + c];
    uint32_t bits = threefry_bits_partitionable(li);
    float eps = bits_to_normal(bits);
    float z = __fadd_rn(mu, __fmul_rn(eps, expf(0.5f * lv)));
    o_z[li]  = z;
    o_mu[li] = mu;
    o_lv[li] = lv;
}

// ---------------- launch ----------------
extern "C" void kernel_launch(void* const* d_in, const int* in_sizes, int n_in,
                              void* d_out, int out_size) {
    const float* x     = (const float*)d_in[0];
    const float* ew    = (const float*)d_in[1];
    const float* W_enc = (const float*)d_in[2];
    const float* b_enc = (const float*)d_in[3];
    const float* W_mu  = (const float*)d_in[4];
    const float* b_mu  = (const float*)d_in[5];
    const float* W_lv  = (const float*)d_in[6];
    const float* b_lv  = (const float*)d_in[7];
    const float* W_dec = (const float*)d_in[8];
    const float* b_dec = (const float*)d_in[9];
    const void*  eidx  = d_in[10];

    float* out   = (float*)d_out;
    float* o_z   = out;                       // [N,64]
    float* o_rec = out + (size_t)NN_ * DL;    // [N,128]
    float* o_mu  = o_rec + (size_t)NN_ * DH;  // [N,64]
    float* o_lv  = o_mu + (size_t)NN_ * DL;   // [N,64]

    float *p_h0, *p_h, *p_agg2, *p_dinv_e, *p_dinv_1, *p_bias2;
    __nv_bfloat16 *p_we_h, *p_we_l, *p_wm_h, *p_wm_l, *p_wd_h, *p_wd_l;
    cudaGetSymbolAddress((void**)&p_h0, g_h0);
    cudaGetSymbolAddress((void**)&p_h, g_h);
    cudaGetSymbolAddress((void**)&p_agg2, g_agg2);
    cudaGetSymbolAddress((void**)&p_dinv_e, g_dinv_e);
    cudaGetSymbolAddress((void**)&p_dinv_1, g_dinv_1);
    cudaGetSymbolAddress((void**)&p_bias2, g_bias2);
    cudaGetSymbolAddress((void**)&p_we_h, g_wt_enc_h);
    cudaGetSymbolAddress((void**)&p_we_l, g_wt_enc_l);
    cudaGetSymbolAddress((void**)&p_wm_h, g_wt_mid_h);
    cudaGetSymbolAddress((void**)&p_wm_l, g_wt_mid_l);
    cudaGetSymbolAddress((void**)&p_wd_h, g_wt_dec_h);
    cudaGetSymbolAddress((void**)&p_wd_l, g_wt_dec_l);

    const int NB_SCAN = (NN_ + 1023) / 1024;           // 98
    const int GEMM_GRID = (NN_ + 127) / 128;           // 782
    const int SMEM128 = 4 * 128 * 136 * 2;             // 139264
    const int SMEM64  = 4 * 128 * 72 * 2;              // 73728

    cudaFuncSetAttribute(hmma_gemm_kernel<128>, cudaFuncAttributeMaxDynamicSharedMemorySize, SMEM128);
    cudaFuncSetAttribute(hmma_gemm_kernel<64>,  cudaFuncAttributeMaxDynamicSharedMemorySize, SMEM64);

    detect_kernel<<<1, 128>>>((const unsigned*)eidx);
    wconv_kernel<<<(128 * 136 + 255) / 256, 256>>>(W_enc, W_mu, W_lv, W_dec);
    init_kernel<<<(NN_ + 255) / 256, 256>>>(b_mu, b_lv);
    deg_kernel<<<(EE_ + 255) / 256, 256>>>(eidx, ew);
    scan1_kernel<<<NB_SCAN, 1024>>>();
    scan2_kernel<<<1, 128>>>(NB_SCAN);
    scan3_kernel<<<(NN_ + 255) / 256, 256>>>();
    fill_kernel<<<(EE_ + 255) / 256, 256>>>(eidx, ew);

    // encoder: h0 = x @ W_enc ; h = agg_w(h0) + b_enc
    hmma_gemm_kernel<128><<<GEMM_GRID, 256, SMEM128>>>(x, NN_, p_we_h, p_we_l, p_h0, nullptr);
    agg_kernel<<<(NN_ * 32 + 255) / 256, 256>>>(p_h0, p_h, p_dinv_e, b_enc, 1);

    // mu|lv: h0 = h @ [W_mu|W_lv] ; agg2 = agg(h0) + [b_mu|b_lv]
    hmma_gemm_kernel<128><<<GEMM_GRID, 256, SMEM128>>>(p_h, NN_, p_wm_h, p_wm_l, p_h0, nullptr);
    agg_kernel<<<(NN_ * 32 + 255) / 256, 256>>>(p_h0, p_agg2, p_dinv_1, p_bias2, 0);

    // reparameterize (writes z, mu, logvar to d_out)
    z_kernel<<<(TOT_CT + 255) / 256, 256>>>(o_z, o_mu, o_lv);

    // decoder (reordered): t = agg(z) [64-dim] ; recon = t @ W_dec + b_dec
    agg64_kernel<<<(NN_ * 32 + 255) / 256, 256>>>(o_z, p_agg2, p_dinv_1);
    hmma_gemm_kernel<64><<<GEMM_GRID, 256, SMEM64>>>(p_agg2, NN_, p_wd_h, p_wd_l, o_rec, b_dec);
}

// round 5
// speedup vs baseline: 1.1964x; 1.0802x over previous
#include <cuda_runtime.h>
#include <cuda_bf16.h>
#include <cuda_fp16.h>
#include <stdint.h>

#define NN_  100000
#define EE_  1600000
#define DH   128
#define DL   64
#define TOT_CT 6400000u   // N*64 elements of eps

// ---------------- device scratch (no cudaMalloc allowed) ----------------
__device__ float  g_h   [NN_ * DH];   // h after encoder agg (fp32, GEMM2 input)
__device__ float  g_agg2[NN_ * DH];   // [mu|lv] agg, later reused as t = A*z (N x 64)
__device__ __half g_hf16[NN_ * DH];   // fp16 GEMM outputs (gather operand)
__device__ __half g_zf16[NN_ * DL];   // fp16 copy of z (decoder gather operand)
__device__ float  g_dinv_e[NN_];
__device__ float  g_dinv_1[NN_];
__device__ int    g_cnt [NN_];
__device__ int    g_base[NN_];
__device__ int    g_fill[NN_];
__device__ int    g_csrc[EE_];
__device__ float  g_cw  [EE_];
__device__ int    g_bsum[128];
__device__ float  g_bias2[DH];
__device__ int    g_is64;

// Preconverted weight operand images: W^T as bf16 hi/lo, row-major [128][KP]
// KP = K + 8 pad (enc/mid K=128 -> KP=136 ; dec K=64 -> KP=72)
__device__ __align__(16) __nv_bfloat16 g_wt_enc_h[128 * 136];
__device__ __align__(16) __nv_bfloat16 g_wt_enc_l[128 * 136];
__device__ __align__(16) __nv_bfloat16 g_wt_mid_h[128 * 136];
__device__ __align__(16) __nv_bfloat16 g_wt_mid_l[128 * 136];
__device__ __align__(16) __nv_bfloat16 g_wt_dec_h[128 * 72];
__device__ __align__(16) __nv_bfloat16 g_wt_dec_l[128 * 72];

// ---------------- edge_index dtype detection ----------------
__global__ void detect_kernel(const unsigned* __restrict__ q) {
    unsigned v = q[threadIdx.x * 2 + 1];
    int any = __syncthreads_or(v != 0u);
    if (threadIdx.x == 0) g_is64 = any ? 0 : 1;
}

__device__ __forceinline__ int2 load_edge(const void* p, int e, int is64) {
    if (is64) {
        const long long* q = (const long long*)p;
        return make_int2((int)q[e], (int)q[EE_ + e]);
    } else {
        const int* q = (const int*)p;
        return make_int2(q[e], q[EE_ + e]);
    }
}

// ---------------- init ----------------
__global__ void init_kernel(const float* __restrict__ b_mu, const float* __restrict__ b_lv) {
    int i = blockIdx.x * blockDim.x + threadIdx.x;
    if (i < NN_) {
        g_cnt[i]  = 0;
        g_fill[i] = 0;
    }
    if (i < DL)       g_bias2[i] = b_mu[i];
    else if (i < DH)  g_bias2[i] = b_lv[i - DL];
}

// ---------------- in-degree count (int only; weighted degree comes from CSR later) ----------------
__global__ void deg_kernel(const void* __restrict__ ei) {
    int e = blockIdx.x * blockDim.x + threadIdx.x;
    if (e >= EE_) return;
    int d;
    if (g_is64) d = (int)((const long long*)ei)[EE_ + e];
    else        d = ((const int*)ei)[EE_ + e];
    atomicAdd(&g_cnt[d], 1);
}

// ---------------- scans ----------------
__global__ void scan1_kernel() {
    __shared__ int sh[1024];
    int i = blockIdx.x * 1024 + threadIdx.x;
    int v = (i < NN_) ? g_cnt[i] : 0;
    sh[threadIdx.x] = v;
    __syncthreads();
    #pragma unroll
    for (int off = 1; off < 1024; off <<= 1) {
        int t = (threadIdx.x >= off) ? sh[threadIdx.x - off] : 0;
        __syncthreads();
        sh[threadIdx.x] += t;
        __syncthreads();
    }
    if (i < NN_) g_base[i] = sh[threadIdx.x] - v;
    if (threadIdx.x == 1023) g_bsum[blockIdx.x] = sh[1023];
}

__global__ void scan2_kernel(int nblocks) {
    __shared__ int sh[128];
    int v = (threadIdx.x < nblocks) ? g_bsum[threadIdx.x] : 0;
    sh[threadIdx.x] = v;
    __syncthreads();
    #pragma unroll
    for (int off = 1; off < 128; off <<= 1) {
        int t = (threadIdx.x >= off) ? sh[threadIdx.x - off] : 0;
        __syncthreads();
        sh[threadIdx.x] += t;
        __syncthreads();
    }
    g_bsum[threadIdx.x] = sh[threadIdx.x] - v;
}

__global__ void scan3_kernel() {
    int i = blockIdx.x * blockDim.x + threadIdx.x;
    if (i >= NN_) return;
    g_base[i] += g_bsum[i >> 10];
    g_dinv_1[i] = rsqrtf((float)g_cnt[i] + 1.0f);
}

// ---------------- CSR fill ----------------
__global__ void fill_kernel(const void* __restrict__ ei, const float* __restrict__ ew) {
    int e = blockIdx.x * blockDim.x + threadIdx.x;
    if (e >= EE_) return;
    int is64 = g_is64;
    int2 sd = load_edge(ei, e, is64);
    int slot = g_base[sd.y] + atomicAdd(&g_fill[sd.y], 1);
    g_csrc[slot] = sd.x;
    g_cw[slot]   = ew[e];
}

// ---------------- weighted degree from CSR rows (contiguous) ----------------
__global__ void sumw_kernel() {
    int i = blockIdx.x * blockDim.x + threadIdx.x;
    if (i >= NN_) return;
    int b = g_base[i], c = g_cnt[i];
    float s = 0.f;
    for (int p = b; p < b + c; p++) s += g_cw[p];
    g_dinv_e[i] = rsqrtf(s + 1.0f);
}

// ---------------- weight convert: W[k][n] -> W^T[n][k] bf16 hi/lo, padded rows ----------------
__device__ __forceinline__ void split_bf16(float v, __nv_bfloat16& h, __nv_bfloat16& l) {
    h = __float2bfloat16(v);
    l = __float2bfloat16(v - __bfloat162float(h));
}

__global__ void wconv_kernel(const float* __restrict__ W_enc, const float* __restrict__ W_mu,
                             const float* __restrict__ W_lv,  const float* __restrict__ W_dec) {
    int idx = blockIdx.x * blockDim.x + threadIdx.x;
    if (idx >= 128 * 136) return;
    int n = idx / 136, k = idx % 136;
    __nv_bfloat16 h, l;
    float ve = (k < 128) ? W_enc[k * 128 + n] : 0.f;
    split_bf16(ve, h, l);
    g_wt_enc_h[idx] = h; g_wt_enc_l[idx] = l;
    float vm = 0.f;
    if (k < 128) vm = (n < 64) ? W_mu[k * 64 + n] : W_lv[k * 64 + (n - 64)];
    split_bf16(vm, h, l);
    g_wt_mid_h[idx] = h; g_wt_mid_l[idx] = l;
    if (k < 72) {
        int di = n * 72 + k;
        float vd = (k < 64) ? W_dec[k * 128 + n] : 0.f;
        split_bf16(vd, h, l);
        g_wt_dec_h[di] = h; g_wt_dec_l[di] = l;
    }
}

// ======================= HMMA GEMM (mma.sync m16n8k16 bf16) =======================
__device__ __forceinline__ uint32_t smem_u32(const void* p) {
    uint32_t a;
    asm("{ .reg .u64 t; cvta.to.shared.u64 t, %1; cvt.u32.u64 %0, t; }" : "=r"(a) : "l"(p));
    return a;
}

__device__ __forceinline__ void ldm_x4(uint32_t addr, uint32_t& r0, uint32_t& r1,
                                       uint32_t& r2, uint32_t& r3) {
    asm volatile("ldmatrix.sync.aligned.m8n8.x4.shared.b16 {%0,%1,%2,%3}, [%4];"
                 : "=r"(r0), "=r"(r1), "=r"(r2), "=r"(r3) : "r"(addr));
}

__device__ __forceinline__ void mma16816(float* c, const uint32_t* a, const uint32_t* b) {
    asm volatile(
        "mma.sync.aligned.m16n8k16.row.col.f32.bf16.bf16.f32 "
        "{%0,%1,%2,%3}, {%4,%5,%6,%7}, {%8,%9}, {%0,%1,%2,%3};"
        : "+f"(c[0]), "+f"(c[1]), "+f"(c[2]), "+f"(c[3])
        : "r"(a[0]), "r"(a[1]), "r"(a[2]), "r"(a[3]), "r"(b[0]), "r"(b[1]));
}

// C[M,128] = A[M,KDIM] @ W^T  with bf16x3 split + optional bias.
// HALF_OUT: write __half C (row stride 128), else float C.
template<int KDIM, bool HALF_OUT>
__global__ void __launch_bounds__(256, 1) hmma_gemm_kernel(
        const float* __restrict__ A, int M,
        const __nv_bfloat16* __restrict__ Bh_img, const __nv_bfloat16* __restrict__ Bl_img,
        void* __restrict__ Cout, const float* __restrict__ bias) {
    constexpr int KP = KDIM + 8;
    constexpr int SZ = 128 * KP;
    extern __shared__ __align__(16) __nv_bfloat16 smem[];
    __nv_bfloat16* sAh = smem;
    __nv_bfloat16* sAl = smem + SZ;
    __nv_bfloat16* sBh = smem + 2 * SZ;
    __nv_bfloat16* sBl = smem + 3 * SZ;

    int tid = threadIdx.x, wid = tid >> 5, lane = tid & 31;
    int rowbase = blockIdx.x * 128;

    // stage B
    {
        const uint4* gh = (const uint4*)Bh_img;
        const uint4* gl = (const uint4*)Bl_img;
        uint4* th = (uint4*)sBh;
        uint4* tl = (uint4*)sBl;
        constexpr int NV = SZ * 2 / 16;
        for (int i = tid; i < NV; i += 256) { th[i] = gh[i]; tl[i] = gl[i]; }
    }

    // stage A: fp32 -> bf16 hi/lo
    {
        constexpr int C4 = KDIM / 4;
        for (int i = tid; i < 128 * C4; i += 256) {
            int row = i / C4, col = (i % C4) * 4;
            float4 av = make_float4(0.f, 0.f, 0.f, 0.f);
            if (rowbase + row < M)
                av = *(const float4*)&A[(size_t)(rowbase + row) * KDIM + col];
            __nv_bfloat16 h0, h1, h2, h3, l0, l1, l2, l3;
            split_bf16(av.x, h0, l0); split_bf16(av.y, h1, l1);
            split_bf16(av.z, h2, l2); split_bf16(av.w, h3, l3);
            uint2 hv, lv;
            hv.x = ((uint32_t)__bfloat16_as_ushort(h1) << 16) | __bfloat16_as_ushort(h0);
            hv.y = ((uint32_t)__bfloat16_as_ushort(h3) << 16) | __bfloat16_as_ushort(h2);
            lv.x = ((uint32_t)__bfloat16_as_ushort(l1) << 16) | __bfloat16_as_ushort(l0);
            lv.y = ((uint32_t)__bfloat16_as_ushort(l3) << 16) | __bfloat16_as_ushort(l2);
            int off = row * KP + col;
            *(uint2*)&sAh[off] = hv;
            *(uint2*)&sAl[off] = lv;
        }
        for (int i = tid; i < 128 * 8 / 4; i += 256) {
            int row = i / 2, seg = i % 2;
            int off = row * KP + KDIM + seg * 4;
            *(uint2*)&sAh[off] = make_uint2(0u, 0u);
            *(uint2*)&sAl[off] = make_uint2(0u, 0u);
        }
    }
    __syncthreads();

    int warp_m = (wid >> 2) * 64;
    int warp_n = (wid & 3) * 32;

    float acc[4][4][4];
    #pragma unroll
    for (int a = 0; a < 4; a++)
        #pragma unroll
        for (int b = 0; b < 4; b++)
            #pragma unroll
            for (int r = 0; r < 4; r++) acc[a][b][r] = 0.f;

    uint32_t sAh_base = smem_u32(sAh), sAl_base = smem_u32(sAl);
    uint32_t sBh_base = smem_u32(sBh), sBl_base = smem_u32(sBl);

    int gA = lane >> 3;
    int a_row_off = (lane & 7) + (gA & 1) * 8;
    int a_col_off = (gA >> 1) * 8;
    int gB = lane >> 3;
    int b_row_off = (lane & 7) + (gB >> 1) * 8;
    int b_col_off = (gB & 1) * 8;

    constexpr int NSTEP = KDIM / 16;
    #pragma unroll
    for (int ks = 0; ks < NSTEP; ks++) {
        int k0 = ks * 16;
        uint32_t bh[4][2], bl[4][2];
        #pragma unroll
        for (int ni2 = 0; ni2 < 2; ni2++) {
            uint32_t off = (uint32_t)((warp_n + ni2 * 16 + b_row_off) * KP + k0 + b_col_off) * 2;
            uint32_t r0, r1, r2, r3;
            ldm_x4(sBh_base + off, r0, r1, r2, r3);
            bh[ni2 * 2 + 0][0] = r0; bh[ni2 * 2 + 0][1] = r1;
            bh[ni2 * 2 + 1][0] = r2; bh[ni2 * 2 + 1][1] = r3;
            ldm_x4(sBl_base + off, r0, r1, r2, r3);
            bl[ni2 * 2 + 0][0] = r0; bl[ni2 * 2 + 0][1] = r1;
            bl[ni2 * 2 + 1][0] = r2; bl[ni2 * 2 + 1][1] = r3;
        }
        #pragma unroll
        for (int mi = 0; mi < 4; mi++) {
            uint32_t off = (uint32_t)((warp_m + mi * 16 + a_row_off) * KP + k0 + a_col_off) * 2;
            uint32_t ah[4], al[4];
            ldm_x4(sAh_base + off, ah[0], ah[1], ah[2], ah[3]);
            ldm_x4(sAl_base + off, al[0], al[1], al[2], al[3]);
            #pragma unroll
            for (int ni = 0; ni < 4; ni++) {
                mma16816(acc[mi][ni], ah, bh[ni]);
                mma16816(acc[mi][ni], ah, bl[ni]);
                mma16816(acc[mi][ni], al, bh[ni]);
            }
        }
    }

    // epilogue
    int qr = lane >> 2;
    int qc = (lane & 3) * 2;
    #pragma unroll
    for (int mi = 0; mi < 4; mi++) {
        int r0 = rowbase + warp_m + mi * 16 + qr;
        #pragma unroll
        for (int ni = 0; ni < 4; ni++) {
            int col = warp_n + ni * 8 + qc;
            float bx = 0.f, by = 0.f;
            if (bias) { bx = bias[col]; by = bias[col + 1]; }
            if (HALF_OUT) {
                __half* Ch = (__half*)Cout;
                if (r0 < M)
                    *(__half2*)&Ch[(size_t)r0 * 128 + col] =
                        __floats2half2_rn(acc[mi][ni][0] + bx, acc[mi][ni][1] + by);
                if (r0 + 8 < M)
                    *(__half2*)&Ch[(size_t)(r0 + 8) * 128 + col] =
                        __floats2half2_rn(acc[mi][ni][2] + bx, acc[mi][ni][3] + by);
            } else {
                float* Cf = (float*)Cout;
                if (r0 < M)
                    *(float2*)&Cf[(size_t)r0 * 128 + col] =
                        make_float2(acc[mi][ni][0] + bx, acc[mi][ni][1] + by);
                if (r0 + 8 < M)
                    *(float2*)&Cf[(size_t)(r0 + 8) * 128 + col] =
                        make_float2(acc[mi][ni][2] + bx, acc[mi][ni][3] + by);
            }
        }
    }
}

// ---------------- aggregation (fp16 gather): one warp per dst node, 128 cols ----------------
__global__ void aggh_kernel(const __half* __restrict__ hin, float* __restrict__ hout,
                            const float* __restrict__ dinv, const float* __restrict__ bias,
                            int use_w) {
    int w = (blockIdx.x * blockDim.x + threadIdx.x) >> 5;
    int lane = threadIdx.x & 31;
    if (w >= NN_) return;
    float dd = dinv[w];
    float4 b4 = *(const float4*)&bias[lane * 4];
    uint2 sraw = *(const uint2*)&hin[(size_t)w * DH + lane * 4];
    float2 s01 = __half22float2(*(__half2*)&sraw.x);
    float2 s23 = __half22float2(*(__half2*)&sraw.y);
    float sn = dd * dd;
    float4 acc;
    acc.x = fmaf(s01.x, sn, b4.x);
    acc.y = fmaf(s01.y, sn, b4.y);
    acc.z = fmaf(s23.x, sn, b4.z);
    acc.w = fmaf(s23.y, sn, b4.w);
    int beg = g_base[w];
    int end = beg + g_cnt[w];
    for (int p = beg; p < end; p++) {
        int s = g_csrc[p];
        float nrm = dinv[s] * dd;
        if (use_w) nrm *= g_cw[p];
        uint2 vr = *(const uint2*)&hin[(size_t)s * DH + lane * 4];
        float2 v01 = __half22float2(*(__half2*)&vr.x);
        float2 v23 = __half22float2(*(__half2*)&vr.y);
        acc.x = fmaf(nrm, v01.x, acc.x);
        acc.y = fmaf(nrm, v01.y, acc.y);
        acc.z = fmaf(nrm, v23.x, acc.z);
        acc.w = fmaf(nrm, v23.y, acc.w);
    }
    *(float4*)&hout[(size_t)w * DH + lane * 4] = acc;
}

// ---------------- aggregation over 64-dim fp16 z (decoder reorder) ----------------
__global__ void agg64h_kernel(const __half* __restrict__ zin, float* __restrict__ t,
                              const float* __restrict__ dinv) {
    int w = (blockIdx.x * blockDim.x + threadIdx.x) >> 5;
    int lane = threadIdx.x & 31;
    if (w >= NN_) return;
    float dd = dinv[w];
    float sn = dd * dd;
    uint32_t sraw = *(const uint32_t*)&zin[(size_t)w * DL + lane * 2];
    float2 sv = __half22float2(*(__half2*)&sraw);
    float2 acc = make_float2(sv.x * sn, sv.y * sn);
    int beg = g_base[w];
    int end = beg + g_cnt[w];
    for (int p = beg; p < end; p++) {
        int s = g_csrc[p];
        float nrm = dinv[s] * dd;
        uint32_t vr = *(const uint32_t*)&zin[(size_t)s * DL + lane * 2];
        float2 v = __half22float2(*(__half2*)&vr);
        acc.x = fmaf(nrm, v.x, acc.x);
        acc.y = fmaf(nrm, v.y, acc.y);
    }
    *(float2*)&t[(size_t)w * DL + lane * 2] = acc;
}

// ---------------- threefry2x32 (JAX key(42)), PARTITIONABLE mode ----------------
__device__ __forceinline__ void tf_round(uint32_t& x0, uint32_t& x1, int r) {
    x0 += x1;
    x1 = (x1 << r) | (x1 >> (32 - r));
    x1 ^= x0;
}

__device__ __forceinline__ uint32_t threefry_bits_partitionable(uint32_t i) {
    const uint32_t ks0 = 0u, ks1 = 42u, ks2 = 0x1BD11BDAu ^ 42u;
    uint32_t x0 = 0u + ks0, x1 = i + ks1;
    tf_round(x0, x1, 13); tf_round(x0, x1, 15); tf_round(x0, x1, 26); tf_round(x0, x1, 6);
    x0 += ks1; x1 += ks2 + 1u;
    tf_round(x0, x1, 17); tf_round(x0, x1, 29); tf_round(x0, x1, 16); tf_round(x0, x1, 24);
    x0 += ks2; x1 += ks0 + 2u;
    tf_round(x0, x1, 13); tf_round(x0, x1, 15); tf_round(x0, x1, 26); tf_round(x0, x1, 6);
    x0 += ks0; x1 += ks1 + 3u;
    tf_round(x0, x1, 17); tf_round(x0, x1, 29); tf_round(x0, x1, 16); tf_round(x0, x1, 24);
    x0 += ks1; x1 += ks2 + 4u;
    tf_round(x0, x1, 13); tf_round(x0, x1, 15); tf_round(x0, x1, 26); tf_round(x0, x1, 6);
    x0 += ks2; x1 += ks0 + 5u;
    return x0 ^ x1;
}

__device__ __forceinline__ float erfinv_xla(float x) {
    float w = -log1pf(-x * x);
    float p;
    if (w < 5.0f) {
        w -= 2.5f;
        p = 2.81022636e-08f;
        p = fmaf(p, w, 3.43273939e-07f);
        p = fmaf(p, w, -3.5233877e-06f);
        p = fmaf(p, w, -4.39150654e-06f);
        p = fmaf(p, w, 0.00021858087f);
        p = fmaf(p, w, -0.00125372503f);
        p = fmaf(p, w, -0.00417768164f);
        p = fmaf(p, w, 0.246640727f);
        p = fmaf(p, w, 1.50140941f);
    } else {
        w = sqrtf(w) - 3.0f;
        p = -0.000200214257f;
        p = fmaf(p, w, 0.000100950558f);
        p = fmaf(p, w, 0.00134934322f);
        p = fmaf(p, w, -0.00367342844f);
        p = fmaf(p, w, 0.00573950773f);
        p = fmaf(p, w, -0.0076224613f);
        p = fmaf(p, w, 0.00943887047f);
        p = fmaf(p, w, 1.00167406f);
        p = fmaf(p, w, 2.83297682f);
    }
    return p * x;
}

__device__ __forceinline__ float bits_to_normal(uint32_t b) {
    float f = __uint_as_float((b >> 9) | 0x3f800000u) - 1.0f;
    const float lo = -0.99999994f;
    float u = __fmul_rn(f, 2.0f);
    u = __fadd_rn(u, lo);
    u = fmaxf(u, lo);
    return 1.4142135623730951f * erfinv_xla(u);
}

__global__ void z_kernel(float* __restrict__ o_z, float* __restrict__ o_mu,
                         float* __restrict__ o_lv) {
    unsigned li = blockIdx.x * blockDim.x + threadIdx.x;
    if (li >= TOT_CT) return;
    unsigned r = li >> 6, c = li & 63u;
    float mu = g_agg2[(size_t)r * DH + c];
    float lv = g_agg2[(size_t)r * DH + DL + c];
    uint32_t bits = threefry_bits_partitionable(li);
    float eps = bits_to_normal(bits);
    float z = __fadd_rn(mu, __fmul_rn(eps, expf(0.5f * lv)));
    o_z[li]  = z;
    o_mu[li] = mu;
    o_lv[li] = lv;
    g_zf16[li] = __float2half_rn(z);
}

// ---------------- launch ----------------
extern "C" void kernel_launch(void* const* d_in, const int* in_sizes, int n_in,
                              void* d_out, int out_size) {
    const float* x     = (const float*)d_in[0];
    const float* ew    = (const float*)d_in[1];
    const float* W_enc = (const float*)d_in[2];
    const float* b_enc = (const float*)d_in[3];
    const float* W_mu  = (const float*)d_in[4];
    const float* b_mu  = (const float*)d_in[5];
    const float* W_lv  = (const float*)d_in[6];
    const float* b_lv  = (const float*)d_in[7];
    const float* W_dec = (const float*)d_in[8];
    const float* b_dec = (const float*)d_in[9];
    const void*  eidx  = d_in[10];

    float* out   = (float*)d_out;
    float* o_z   = out;                       // [N,64]
    float* o_rec = out + (size_t)NN_ * DL;    // [N,128]
    float* o_mu  = o_rec + (size_t)NN_ * DH;  // [N,64]
    float* o_lv  = o_mu + (size_t)NN_ * DL;   // [N,64]

    float *p_h, *p_agg2, *p_dinv_e, *p_dinv_1, *p_bias2;
    __half *p_hf16, *p_zf16;
    __nv_bfloat16 *p_we_h, *p_we_l, *p_wm_h, *p_wm_l, *p_wd_h, *p_wd_l;
    cudaGetSymbolAddress((void**)&p_h, g_h);
    cudaGetSymbolAddress((void**)&p_agg2, g_agg2);
    cudaGetSymbolAddress((void**)&p_hf16, g_hf16);
    cudaGetSymbolAddress((void**)&p_zf16, g_zf16);
    cudaGetSymbolAddress((void**)&p_dinv_e, g_dinv_e);
    cudaGetSymbolAddress((void**)&p_dinv_1, g_dinv_1);
    cudaGetSymbolAddress((void**)&p_bias2, g_bias2);
    cudaGetSymbolAddress((void**)&p_we_h, g_wt_enc_h);
    cudaGetSymbolAddress((void**)&p_we_l, g_wt_enc_l);
    cudaGetSymbolAddress((void**)&p_wm_h, g_wt_mid_h);
    cudaGetSymbolAddress((void**)&p_wm_l, g_wt_mid_l);
    cudaGetSymbolAddress((void**)&p_wd_h, g_wt_dec_h);
    cudaGetSymbolAddress((void**)&p_wd_l, g_wt_dec_l);

    const int NB_SCAN = (NN_ + 1023) / 1024;           // 98
    const int GEMM_GRID = (NN_ + 127) / 128;           // 782
    const int SMEM128 = 4 * 128 * 136 * 2;             // 139264
    const int SMEM64  = 4 * 128 * 72 * 2;              // 73728

    cudaFuncSetAttribute(hmma_gemm_kernel<128, true>,  cudaFuncAttributeMaxDynamicSharedMemorySize, SMEM128);
    cudaFuncSetAttribute(hmma_gemm_kernel<64, false>,  cudaFuncAttributeMaxDynamicSharedMemorySize, SMEM64);

    detect_kernel<<<1, 128>>>((const unsigned*)eidx);
    wconv_kernel<<<(128 * 136 + 255) / 256, 256>>>(W_enc, W_mu, W_lv, W_dec);
    init_kernel<<<(NN_ + 255) / 256, 256>>>(b_mu, b_lv);
    deg_kernel<<<(EE_ + 255) / 256, 256>>>(eidx);
    scan1_kernel<<<NB_SCAN, 1024>>>();
    scan2_kernel<<<1, 128>>>(NB_SCAN);
    scan3_kernel<<<(NN_ + 255) / 256, 256>>>();
    fill_kernel<<<(EE_ + 255) / 256, 256>>>(eidx, ew);
    sumw_kernel<<<(NN_ + 255) / 256, 256>>>();

    // encoder: hf16 = x @ W_enc ; h = agg_w(hf16) + b_enc
    hmma_gemm_kernel<128, true><<<GEMM_GRID, 256, SMEM128>>>(x, NN_, p_we_h, p_we_l, p_hf16, nullptr);
    aggh_kernel<<<(NN_ * 32 + 255) / 256, 256>>>(p_hf16, p_h, p_dinv_e, b_enc, 1);

    // mu|lv: hf16 = h @ [W_mu|W_lv] ; agg2 = agg(hf16) + [b_mu|b_lv]
    hmma_gemm_kernel<128, true><<<GEMM_GRID, 256, SMEM128>>>(p_h, NN_, p_wm_h, p_wm_l, p_hf16, nullptr);
    aggh_kernel<<<(NN_ * 32 + 255) / 256, 256>>>(p_hf16, p_agg2, p_dinv_1, p_bias2, 0);

    // reparameterize (writes z, mu, logvar to d_out; also fp16 z copy)
    z_kernel<<<(TOT_CT + 255) / 256, 256>>>(o_z, o_mu, o_lv);

    // decoder (reordered): t = agg(z_fp16) [64-dim] ; recon = t @ W_dec + b_dec
    agg64h_kernel<<<(NN_ * 32 + 255) / 256, 256>>>(p_zf16, p_agg2, p_dinv_1);
    hmma_gemm_kernel<64, false><<<GEMM_GRID, 256, SMEM64>>>(p_agg2, NN_, p_wd_h, p_wd_l, o_rec, b_dec);
}